// round 10
// baseline (speedup 1.0000x reference)
#include <cuda_runtime.h>

// SparseAbacusLayer: out[b,n] = prod_d (1 - interp1d(clip(act[b,:]), linspace(0,1,N_in), sp[n,d]))
// B=128, N_in=N_out=65536, degree=2.
//
// R10 (= R9 resubmit after infra failure): main kernel is latency-bound
// (issue 43.9%, occ 43.7%, all mem pipes <32%). (a) launch_bounds(256,5):
// 48-reg budget -> 5 blocks/SM. (b) meta solve made warp-local (lanes 0..7
// solve, shfl broadcast): removes the leading __syncthreads + smem meta
// round-trip so every warp starts its gathers immediately.

#define N_IN   65536
#define N_OUT  65536
#define NB     128

// clipped, transposed, u16-quantized activations: (N_in, B) -> 16 MB
__device__ __align__(16) unsigned short g_act16[N_IN * NB];

__device__ __forceinline__ float clip01(float v) {
    return fminf(fmaxf(v, 0.0f), 1.0f);
}

// two u16 -> two floats in [0,65535] via exponent-splice (PRMT + FADD)
__device__ __forceinline__ void cvt2(unsigned int w, float& lo, float& hi) {
    lo = __uint_as_float(__byte_perm(w, 0x4B000000u, 0x7410)) - 8388608.0f;
    hi = __uint_as_float(__byte_perm(w, 0x4B000000u, 0x7432)) - 8388608.0f;
}

// x[i] = fl(i * fl(1/65535)) matches jnp.linspace(0,1,65536,f32) exactly.
__device__ __forceinline__ void solve_point(float spv, int& idx, float& w) {
    const float DELTA = 1.0f / 65535.0f;
    spv = clip01(spv);
    int g = (int)(spv * 65535.0f);
    g = min(max(g, 0), 65535);
    while (g < 65535 && __fmul_rn((float)g, DELTA) < spv) ++g;
    while (g > 0 && __fmul_rn((float)(g - 1), DELTA) >= spv) --g;
    idx = max(g - 1, 0);                       // <= 65534
    float x0 = __fmul_rn((float)idx, DELTA);
    float x1 = __fmul_rn((float)(idx + 1), DELTA);
    float dx = __fadd_rn(__fsub_rn(x1, x0), 1e-8f);
    w = __fdiv_rn(__fsub_rn(spv, x0), dx);
}

// Clip+transpose+quantize: act (B,N_in) fp32 -> act16 (N_in,B) u16.
// Block (8,32) handles 32 n x ALL 128 b via four 32x33 tiles (MLP=4/thread).
__global__ void __launch_bounds__(256)
transpose_clip_kernel(const float* __restrict__ act) {
    __shared__ float tile[4][32][33];           // [b_tile][n_local][b_local]
    const int tx = threadIdx.x;                 // 0..7
    const int ty = threadIdx.y;                 // 0..31
    const int n0 = blockIdx.x * 32;

    float4 v[4];
    #pragma unroll
    for (int j = 0; j < 4; ++j)
        v[j] = __ldcs(reinterpret_cast<const float4*>(
            &act[(size_t)(32 * j + ty) * N_IN + n0 + 4 * tx]));

    #pragma unroll
    for (int j = 0; j < 4; ++j) {
        // STS.32 x4: bank = (4tx + i + ty) mod 32 -> conflict-free
        tile[j][4 * tx + 0][ty] = clip01(v[j].x);
        tile[j][4 * tx + 1][ty] = clip01(v[j].y);
        tile[j][4 * tx + 2][ty] = clip01(v[j].z);
        tile[j][4 * tx + 3][ty] = clip01(v[j].w);
    }
    __syncthreads();

    #pragma unroll
    for (int j = 0; j < 4; ++j) {
        // LDS.32 x4: bank = (ty + 4tx + i) mod 32 -> conflict-free
        unsigned int u0 = __float2uint_rn(tile[j][ty][4 * tx + 0] * 65535.0f);
        unsigned int u1 = __float2uint_rn(tile[j][ty][4 * tx + 1] * 65535.0f);
        unsigned int u2 = __float2uint_rn(tile[j][ty][4 * tx + 2] * 65535.0f);
        unsigned int u3 = __float2uint_rn(tile[j][ty][4 * tx + 3] * 65535.0f);
        uint2 p;
        p.x = u0 | (u1 << 16);
        p.y = u2 | (u3 << 16);
        *reinterpret_cast<uint2*>(
            &g_act16[(size_t)(n0 + ty) * NB + 32 * j + 4 * tx]) = p;
    }
}

// Main kernel: block = 32 consecutive n x all 128 b.
// Warp w handles n = n0+4w..+3; lane covers b = 4*lane..4*lane+3 (one uint2).
// Meta solved warp-locally: lanes 0..7 solve the warp's 8 points, shfl bcast.
__global__ void __launch_bounds__(256, 5)
interp_main_kernel(const float* __restrict__ sp, float* __restrict__ out) {
    __shared__ float tile[32 * 128];            // swizzled staging, 16 KB

    const int n0 = blockIdx.x * 32;
    const int tid = threadIdx.x;
    const int warp = tid >> 5;
    const int lane = tid & 31;
    const float S = 1.0f / 65535.0f;

    // lanes 0..7: solve point (k = lane>>1, d = lane&1) for n = n0+4*warp+k
    int sidx = 0; float sw = 0.0f;
    if (lane < 8) {
        float spv = sp[(size_t)(n0 + 4 * warp + (lane >> 1)) * 2 + (lane & 1)];
        solve_point(spv, sidx, sw);
    }

    int i0[4], i1[4]; float w0[4], w1[4];
    #pragma unroll
    for (int k = 0; k < 4; ++k) {
        i0[k] = __shfl_sync(0xFFFFFFFFu, sidx, 2 * k);
        w0[k] = __shfl_sync(0xFFFFFFFFu, sw,   2 * k);
        i1[k] = __shfl_sync(0xFFFFFFFFu, sidx, 2 * k + 1);
        w1[k] = __shfl_sync(0xFFFFFFFFu, sw,   2 * k + 1);
    }

    // rows are 128 u16 = 32 uint2
    uint2 u00[4], u01[4], u10[4], u11[4];
    #pragma unroll
    for (int k = 0; k < 4; ++k) {
        const uint2* r0 = reinterpret_cast<const uint2*>(
            g_act16 + (size_t)i0[k] * NB);
        const uint2* r1 = reinterpret_cast<const uint2*>(
            g_act16 + (size_t)i1[k] * NB);
        u00[k] = __ldg(r0 + lane);
        u01[k] = __ldg(r0 + 32 + lane);
        u10[k] = __ldg(r1 + lane);
        u11[k] = __ldg(r1 + 32 + lane);
    }

    #pragma unroll
    for (int k = 0; k < 4; ++k) {
        const int nl = warp * 4 + k;
        float a00[4], a01[4], a10[4], a11[4];
        cvt2(u00[k].x, a00[0], a00[1]); cvt2(u00[k].y, a00[2], a00[3]);
        cvt2(u01[k].x, a01[0], a01[1]); cvt2(u01[k].y, a01[2], a01[3]);
        cvt2(u10[k].x, a10[0], a10[1]); cvt2(u10[k].y, a10[2], a10[3]);
        cvt2(u11[k].x, a11[0], a11[1]); cvt2(u11[k].y, a11[2], a11[3]);

        float res[4];
        #pragma unroll
        for (int i = 0; i < 4; ++i) {
            float t0 = fmaf(a01[i] - a00[i], w0[k], a00[i]);  // in [0,65535]
            float t1 = fmaf(a11[i] - a10[i], w1[k], a10[i]);
            res[i] = fmaf(t0, -S, 1.0f) * fmaf(t1, -S, 1.0f);
        }
        // STS.128: quad col = lane ^ warp -> conflict-free
        float4 r4 = make_float4(res[0], res[1], res[2], res[3]);
        *reinterpret_cast<float4*>(&tile[nl * 128 + 4 * (lane ^ warp)]) = r4;
    }
    __syncthreads();

    // Output: thread (q = lane&7, bi = lane>>3) emits float4 along n for one b.
    const int q = lane & 7;
    const int bi = lane >> 3;
    #pragma unroll
    for (int it = 0; it < 4; ++it) {
        const int b = 4 * warp + bi + 32 * it;
        const int B = b >> 2;                   // = warp + 8*it (bi < 4)
        float vv[4];
        #pragma unroll
        for (int i = 0; i < 4; ++i) {
            // LDS.32: bank = (4*(B^q) + bi) mod 32 -> conflict-free
            vv[i] = tile[(4 * q + i) * 128 + 4 * (B ^ q) + bi];
        }
        // STG.128: per warp, 4 consecutive b rows x 128B each -> coalesced
        float4 o = make_float4(vv[0], vv[1], vv[2], vv[3]);
        __stcs(reinterpret_cast<float4*>(&out[(size_t)b * N_OUT + n0 + 4 * q]), o);
    }
}

extern "C" void kernel_launch(void* const* d_in, const int* in_sizes, int n_in,
                              void* d_out, int out_size) {
    const float* act = (const float*)d_in[0];   // (128, 65536) fp32
    const float* sp  = (const float*)d_in[1];   // (65536, 2, 1) fp32
    float* out = (float*)d_out;                 // (128, 65536) fp32
    (void)in_sizes; (void)n_in; (void)out_size;

    transpose_clip_kernel<<<N_IN / 32, dim3(8, 32)>>>(act);
    interp_main_kernel<<<N_OUT / 32, 256>>>(sp, out);
}